// round 4
// baseline (speedup 1.0000x reference)
#include <cuda_runtime.h>
#include <cstdint>

// Problem shape
#define NB 16
#define NQ 2048
#define NK 2048
#define ND 128
// Tiling
#define BQ 64
#define BK 64
#define NTHREADS 256

typedef unsigned long long u64;

// ---------------------------------------------------------------------------
// f32x2 packed math (sm_100+; PTX only)
// ---------------------------------------------------------------------------
__device__ __forceinline__ u64 pk2(float lo, float hi) {
    u64 r; asm("mov.b64 %0, {%1, %2};" : "=l"(r) : "f"(lo), "f"(hi)); return r;
}
__device__ __forceinline__ void upk2(u64 v, float& lo, float& hi) {
    asm("mov.b64 {%0, %1}, %2;" : "=f"(lo), "=f"(hi) : "l"(v));
}
__device__ __forceinline__ u64 f2fma(u64 a, u64 b, u64 c) {
    u64 d; asm("fma.rn.f32x2 %0, %1, %2, %3;" : "=l"(d) : "l"(a), "l"(b), "l"(c)); return d;
}
__device__ __forceinline__ u64 f2mul(u64 a, u64 b) {
    u64 d; asm("mul.rn.f32x2 %0, %1, %2;" : "=l"(d) : "l"(a), "l"(b)); return d;
}

// ---------------------------------------------------------------------------
// JAX Threefry-2x32, key=[0,42]; partitionable: counter=(0,i), bits=x0^x1,
// keep <=> (bits>>9) < 5872026  (exact integer form of u<0.7f)
// ---------------------------------------------------------------------------
__device__ __forceinline__ uint32_t rotl32(uint32_t x, uint32_t r) {
    return __funnelshift_l(x, x, r);
}
__device__ __forceinline__ bool keep_bit(uint32_t i) {
    const uint32_t ks1 = 42u;
    const uint32_t ks2 = 42u ^ 0x1BD11BDAu;
    uint32_t x0 = 0u, x1 = i + ks1;
#define TF_R(r) { x0 += x1; x1 = rotl32(x1, (r)); x1 ^= x0; }
    TF_R(13) TF_R(15) TF_R(26) TF_R(6)
    x0 += ks1; x1 += ks2 + 1u;
    TF_R(17) TF_R(29) TF_R(16) TF_R(24)
    x0 += ks2; x1 += 2u;
    TF_R(13) TF_R(15) TF_R(26) TF_R(6)
    x1 += ks1 + 3u;
    TF_R(17) TF_R(29) TF_R(16) TF_R(24)
    x0 += ks1; x1 += ks2 + 4u;
    TF_R(13) TF_R(15) TF_R(26) TF_R(6)
    x0 += ks2; x1 += 5u;
#undef TF_R
    return ((x0 ^ x1) >> 9) < 5872026u;
}

// K-tile swizzle: float4-granular XOR so stride can stay 128 floats.
// word offset of float4 index f4 in row `row`
__device__ __forceinline__ int swz(int row, int f4) {
    return row * 128 + (((f4) ^ (row & 7)) << 2);
}

// ---------------------------------------------------------------------------
// Fused flash attention: cp.async double-buffered K, reg softmax, inline RNG
// ---------------------------------------------------------------------------
__global__ void __launch_bounds__(NTHREADS, 2)
attn_kernel(const float* __restrict__ x1, const float* __restrict__ x2,
            float* __restrict__ out) {
    extern __shared__ float sm[];
    float* sQ = sm;                   // [64][128]
    float* sK = sQ + BQ * ND;         // [2][64][128] swizzled
    float* sS = sK + 2 * BK * ND;     // [64][64]   P tile
    float* sA = sS + BQ * BK;         // [64]       alpha (loop) / l (epilogue)

    const int b   = blockIdx.y;
    const int q0  = blockIdx.x * BQ;
    const int tid = threadIdx.x;
    const int tx  = tid & 15;         // GEMM1: cols tx+16j
    const int ty  = tid >> 4;         // GEMM1: rows ty*4+i
    const int cg  = tid & 31;         // GEMM2: float4-col index (floats 4cg..4cg+3)
    const int rg  = tid >> 5;         // GEMM2: rows rg*8+i

    const uint32_t sK_u32 = (uint32_t)__cvta_generic_to_shared(sK);

    // Q tile load (global -> smem, plain layout; overlaps first cp.async)
    const float* gq = x1 + (size_t)(b * NQ + q0) * ND;
    const float* gk0 = x2 + (size_t)b * NK * ND;

    // prologue: async-load K tile 0 into buffer 0
    {
        const float* g = gk0;
#pragma unroll
        for (int it = 0; it < 8; it++) {
            int t = tid + it * NTHREADS;
            int row = t >> 5, d4 = t & 31;
            uint32_t dst = sK_u32 + (uint32_t)(swz(row, d4) * 4);
            const float* src = g + row * ND + d4 * 4;
            asm volatile("cp.async.cg.shared.global [%0], [%1], 16;\n"
                         :: "r"(dst), "l"(src));
        }
        asm volatile("cp.async.commit_group;\n");
    }
    for (int t = tid; t < BQ * ND / 4; t += NTHREADS) {
        int row = t >> 5, c = (t & 31) << 2;
        *(float4*)(sQ + row * ND + c) = *(const float4*)(gq + row * ND + c);
    }

    // per-row softmax state (GEMM1 mapping)
    float m_i[4], l_i[4];
    uint32_t rb[4];
#pragma unroll
    for (int i = 0; i < 4; i++) {
        m_i[i] = -1e30f; l_i[i] = 0.0f;
        rb[i] = (uint32_t)(b * NQ + q0 + ty * 4 + i) * (uint32_t)NK;
    }

    u64 oacc[8][2];                   // GEMM2 mapping: rows rg*8+i, cols 4cg+{0..3}
#pragma unroll
    for (int i = 0; i < 8; i++) { oacc[i][0] = 0ull; oacc[i][1] = 0ull; }

    // GEMM1 sK row bases (swizzle precompute)
    int rowoff[4], rs[4];
#pragma unroll
    for (int j = 0; j < 4; j++) {
        int row = tx + 16 * j;
        rowoff[j] = row * 128;
        rs[j] = row & 7;
    }

    for (int kt = 0; kt < NK / BK; ++kt) {
        __syncthreads();              // GEMM2(kt-1) done: safe to overwrite buf[(kt+1)&1]
        // prefetch next K tile ((kt+1)&31: last iter redundantly reloads tile 0 — safe)
        {
            const float* g = gk0 + (size_t)(((kt + 1) & 31) * BK) * ND;
            uint32_t dstb = sK_u32 + (uint32_t)(((kt + 1) & 1) * BK * ND * 4);
#pragma unroll
            for (int it = 0; it < 8; it++) {
                int t = tid + it * NTHREADS;
                int row = t >> 5, d4 = t & 31;
                uint32_t dst = dstb + (uint32_t)(swz(row, d4) * 4);
                const float* src = g + row * ND + d4 * 4;
                asm volatile("cp.async.cg.shared.global [%0], [%1], 16;\n"
                             :: "r"(dst), "l"(src));
            }
            asm volatile("cp.async.commit_group;\n");
        }
        asm volatile("cp.async.wait_group 1;\n");   // buf[kt&1] complete
        __syncthreads();                            // visible to all warps

        const float* sKc = sK + (kt & 1) * BK * ND;
        const int k0 = kt * BK;

        // ---- GEMM1: S = Q @ K^T (4x4 per thread)
        u64 s2[4][4];
#pragma unroll
        for (int i = 0; i < 4; i++)
#pragma unroll
            for (int j = 0; j < 4; j++) s2[i][j] = 0ull;

        for (int d0 = 0; d0 < ND; d0 += 4) {
            const int d4 = d0 >> 2;
            float4 a4[4], b4[4];
#pragma unroll
            for (int i = 0; i < 4; i++)
                a4[i] = *(const float4*)(sQ + (ty * 4 + i) * ND + d0);
#pragma unroll
            for (int j = 0; j < 4; j++)
                b4[j] = *(const float4*)(sKc + rowoff[j] + ((d4 ^ rs[j]) << 2));
            u64 blo[4], bhi[4];
#pragma unroll
            for (int j = 0; j < 4; j++) {
                blo[j] = pk2(b4[j].x, b4[j].y);
                bhi[j] = pk2(b4[j].z, b4[j].w);
            }
#pragma unroll
            for (int i = 0; i < 4; i++) {
                u64 alo = pk2(a4[i].x, a4[i].y);
                u64 ahi = pk2(a4[i].z, a4[i].w);
#pragma unroll
                for (int j = 0; j < 4; j++) {
                    s2[i][j] = f2fma(alo, blo[j], s2[i][j]);
                    s2[i][j] = f2fma(ahi, bhi[j], s2[i][j]);
                }
            }
        }

        // ---- register online softmax + inline threefry dropout
#pragma unroll
        for (int i = 0; i < 4; i++) {
            float s[4];
            float mx = -1e30f;
#pragma unroll
            for (int j = 0; j < 4; j++) {
                float lo, hi; upk2(s2[i][j], lo, hi);
                s[j] = (lo + hi) * 1.153f;
                mx = fmaxf(mx, s[j]);
            }
#pragma unroll
            for (int off = 1; off < 16; off <<= 1)
                mx = fmaxf(mx, __shfl_xor_sync(0xffffffffu, mx, off));
            float mnew  = fmaxf(m_i[i], mx);
            float alpha = __expf(m_i[i] - mnew);
            m_i[i] = mnew;

            float sum = 0.0f;
            float p[4];
            uint32_t base = rb[i] + (uint32_t)(k0 + tx);
#pragma unroll
            for (int j = 0; j < 4; j++) {
                float e = __expf(s[j] - mnew);
                sum += e;                           // unmasked denominator
                p[j] = keep_bit(base + 16u * j) ? e : 0.0f;
            }
#pragma unroll
            for (int off = 1; off < 16; off <<= 1)
                sum += __shfl_xor_sync(0xffffffffu, sum, off);
            l_i[i] = l_i[i] * alpha + sum;

            float* srow = sS + (ty * 4 + i) * BK;
#pragma unroll
            for (int j = 0; j < 4; j++) srow[tx + 16 * j] = p[j];
            if (tx == 0) sA[ty * 4 + i] = alpha;
        }
        __syncthreads();              // P + alpha ready

        // ---- GEMM2 (remapped): rows rg*8+i, cols 4cg..4cg+3
#pragma unroll
        for (int i = 0; i < 8; i++) {
            float a = sA[rg * 8 + i];
            u64 a2 = pk2(a, a);
            oacc[i][0] = f2mul(oacc[i][0], a2);
            oacc[i][1] = f2mul(oacc[i][1], a2);
        }
#pragma unroll 2
        for (int kk0 = 0; kk0 < BK; kk0 += 4) {
            float4 p4[8];
#pragma unroll
            for (int i = 0; i < 8; i++)
                p4[i] = *(const float4*)(sS + (rg * 8 + i) * BK + kk0);
#pragma unroll
            for (int dd = 0; dd < 4; dd++) {
                float4 vv = *(const float4*)(sKc + swz(kk0 + dd, cg));
                u64 vlo = pk2(vv.x, vv.y), vhi = pk2(vv.z, vv.w);
#pragma unroll
                for (int i = 0; i < 8; i++) {
                    float pv = ((const float*)&p4[i])[dd];
                    u64 pb = pk2(pv, pv);
                    oacc[i][0] = f2fma(pb, vlo, oacc[i][0]);
                    oacc[i][1] = f2fma(pb, vhi, oacc[i][1]);
                }
            }
        }
    }

    // ---- epilogue: publish l, then out = acc / (0.7 * l)
    __syncthreads();
    if (tx == 0) {
#pragma unroll
        for (int i = 0; i < 4; i++) sA[ty * 4 + i] = l_i[i];
    }
    __syncthreads();
#pragma unroll
    for (int i = 0; i < 8; i++) {
        float inv = 1.0f / (0.7f * sA[rg * 8 + i]);
        u64 inv2 = pk2(inv, inv);
        u64 o0 = f2mul(oacc[i][0], inv2);
        u64 o1 = f2mul(oacc[i][1], inv2);
        float4 st;
        upk2(o0, st.x, st.y);
        upk2(o1, st.z, st.w);
        float* grow = out + (size_t)(b * NQ + q0 + rg * 8 + i) * ND;
        *(float4*)(grow + 4 * cg) = st;
    }
}

// ---------------------------------------------------------------------------
extern "C" void kernel_launch(void* const* d_in, const int* in_sizes, int n_in,
                              void* d_out, int out_size) {
    const float* x1 = (const float*)d_in[0];
    const float* x2 = (const float*)d_in[1];
    float* out = (float*)d_out;

    size_t smem = (size_t)(BQ * ND + 2 * BK * ND + BQ * BK + 64) * sizeof(float); // 114,944 B
    cudaFuncSetAttribute(attn_kernel,
                         cudaFuncAttributeMaxDynamicSharedMemorySize, (int)smem);
    dim3 grid(NQ / BQ, NB);
    attn_kernel<<<grid, NTHREADS, smem>>>(x1, x2, out);
}